// round 3
// baseline (speedup 1.0000x reference)
#include <cuda_runtime.h>

// ---------------------------------------------------------------------------
// Problem constants
// ---------------------------------------------------------------------------
#define Bn   4
#define Ln   2048
#define Dn   1024
#define Hn   16
#define Kd   64
#define LDf  (Ln * Dn)      // 2097152 floats per batch
#define HSTR (Ln * Kd)      // 131072: contiguous per-head [2048,64] block

// ---------------------------------------------------------------------------
// Scratch (static __device__ — allocation-free rule)
// ---------------------------------------------------------------------------
__device__ float g_q[Bn * LDf];                   // 32 MB
__device__ float g_k[Bn * LDf];                   // 32 MB
__device__ float g_v[Bn * LDf];                   // 32 MB
__device__ float g_att[Bn * LDf];                 // 32 MB (concatted layout)
__device__ float g_zinv[(size_t)Bn * Ln * Ln];    // 64 MB

// ---------------------------------------------------------------------------
// Packed f32x2 FMA (Blackwell): 2 FMA per instruction, restores full fp32 rate
// ---------------------------------------------------------------------------
__device__ __forceinline__ void fma2(float2 &c, float2 a, float2 b) {
    unsigned long long &cu = reinterpret_cast<unsigned long long &>(c);
    const unsigned long long &au = reinterpret_cast<const unsigned long long &>(a);
    const unsigned long long &bu = reinterpret_cast<const unsigned long long &>(b);
    asm("fma.rn.f32x2 %0, %1, %2, %0;" : "+l"(cu) : "l"(au), "l"(bu));
}

// ---------------------------------------------------------------------------
// SGEMM: C[M,1024-wide dest] tile = A[M,1024] @ Bw[1024,Nld]
// 128x128 tile, BK=16, 256 threads, 8x8 micro-tile (f32x2 pairs along n).
// mode 0: A = Aext (x), dest split g_q/g_k/g_v by 1024-column part (QKV)
// mode 1: A = g_att,     dest = Cext (output projection)
// ---------------------------------------------------------------------------
__global__ __launch_bounds__(256, 2) void sgemm128(
    const float* __restrict__ Aext, const float* __restrict__ Bw,
    float* __restrict__ Cext, int Nld, int mode)
{
    __shared__ __align__(16) float As[16][132];   // k-major (transposed A)
    __shared__ __align__(16) float Bs[16][132];   // k-major (natural B)

    const float* __restrict__ A = mode ? g_att : Aext;

    const int t  = threadIdx.x;
    const int tx = t & 15, ty = t >> 4;
    const int m0 = blockIdx.y * 128;
    const int n0 = blockIdx.x * 128;

    float* C;
    int nloc;
    if (mode == 0) {
        int part = n0 >> 10;
        C = (part == 0) ? g_q : ((part == 1) ? g_k : g_v);
        nloc = n0 & 1023;
    } else {
        C = Cext;
        nloc = n0;
    }

    float2 acc[8][4];
#pragma unroll
    for (int i = 0; i < 8; i++)
#pragma unroll
        for (int j = 0; j < 4; j++) acc[i][j] = make_float2(0.f, 0.f);

    const int ar  = t >> 2;   // 0..63 (A row pair)
    const int ac4 = t & 3;    // 0..3  (A k-float4)
    const int bk  = t >> 5;   // 0..7  (B k row)
    const int bn4 = t & 31;   // 0..31 (B n-float4)

    for (int k0 = 0; k0 < 1024; k0 += 16) {
        __syncthreads();
#pragma unroll
        for (int h = 0; h < 2; h++) {
            int row = ar + h * 64;
            float4 v = *(const float4*)(A + (size_t)(m0 + row) * 1024 + k0 + ac4 * 4);
            As[ac4 * 4 + 0][row] = v.x;
            As[ac4 * 4 + 1][row] = v.y;
            As[ac4 * 4 + 2][row] = v.z;
            As[ac4 * 4 + 3][row] = v.w;
        }
#pragma unroll
        for (int h = 0; h < 2; h++) {
            int kr = bk + h * 8;
            *(float4*)&Bs[kr][bn4 * 4] =
                *(const float4*)(Bw + (size_t)(k0 + kr) * Nld + n0 + bn4 * 4);
        }
        __syncthreads();
#pragma unroll
        for (int kk = 0; kk < 16; kk++) {
            float4 a0 = *(const float4*)&As[kk][ty * 4];
            float4 a1 = *(const float4*)&As[kk][64 + ty * 4];
            float4 b0 = *(const float4*)&Bs[kk][tx * 4];
            float4 b1 = *(const float4*)&Bs[kk][64 + tx * 4];
            float  av[8] = {a0.x, a0.y, a0.z, a0.w, a1.x, a1.y, a1.z, a1.w};
            float2 bp[4] = {make_float2(b0.x, b0.y), make_float2(b0.z, b0.w),
                            make_float2(b1.x, b1.y), make_float2(b1.z, b1.w)};
#pragma unroll
            for (int i = 0; i < 8; i++) {
                float2 a2 = make_float2(av[i], av[i]);
#pragma unroll
                for (int j = 0; j < 4; j++) fma2(acc[i][j], a2, bp[j]);
            }
        }
    }

#pragma unroll
    for (int i = 0; i < 8; i++) {
        int row = m0 + ((i < 4) ? (ty * 4 + i) : (64 + ty * 4 + i - 4));
        float4 v0 = make_float4(acc[i][0].x, acc[i][0].y, acc[i][1].x, acc[i][1].y);
        float4 v1 = make_float4(acc[i][2].x, acc[i][2].y, acc[i][3].x, acc[i][3].y);
        *(float4*)(C + (size_t)row * 1024 + nloc + tx * 4)      = v0;
        *(float4*)(C + (size_t)row * 1024 + nloc + 64 + tx * 4) = v1;
    }
}

// ---------------------------------------------------------------------------
// Pass A: zinv[b,l,m] = 1 / sum_h exp(Q_h[l]·K_h[m] / 8)
// CTA: one (b, 128-l-tile, 128-m-tile); loop over 16 heads; 8x8 micro-tile.
// Dynamic smem: Qs[64][132] + Ks[64][132] = 67584 B.
// ---------------------------------------------------------------------------
__global__ __launch_bounds__(256) void zsum_kernel()
{
    extern __shared__ float sm[];
    float (*Qs)[132] = (float(*)[132])sm;
    float (*Ks)[132] = (float(*)[132])(sm + 64 * 132);

    const int t  = threadIdx.x;
    const int tx = t & 15, ty = t >> 4;
    const int m0 = blockIdx.x * 128;
    const int l0 = blockIdx.y * 128;
    const int b  = blockIdx.z;

    const int lr = t & 127;    // load row
    const int lc = t >> 7;     // 0..1

    float2 zs[8][4];
#pragma unroll
    for (int i = 0; i < 8; i++)
#pragma unroll
        for (int j = 0; j < 4; j++) zs[i][j] = make_float2(0.f, 0.f);

    for (int h = 0; h < Hn; h++) {
        const float* __restrict__ Qb = g_q + (size_t)b * LDf + (size_t)h * HSTR + (size_t)l0 * Kd;
        const float* __restrict__ Kb = g_k + (size_t)b * LDf + (size_t)h * HSTR + (size_t)m0 * Kd;
        __syncthreads();
#pragma unroll
        for (int c = 0; c < 8; c++) {
            int c4 = lc + c * 2;   // 0..15
            float4 q = *(const float4*)(Qb + lr * Kd + c4 * 4);
            Qs[c4 * 4 + 0][lr] = q.x;  Qs[c4 * 4 + 1][lr] = q.y;
            Qs[c4 * 4 + 2][lr] = q.z;  Qs[c4 * 4 + 3][lr] = q.w;
            float4 kv = *(const float4*)(Kb + lr * Kd + c4 * 4);
            Ks[c4 * 4 + 0][lr] = kv.x; Ks[c4 * 4 + 1][lr] = kv.y;
            Ks[c4 * 4 + 2][lr] = kv.z; Ks[c4 * 4 + 3][lr] = kv.w;
        }
        __syncthreads();

        float2 s[8][4];
#pragma unroll
        for (int i = 0; i < 8; i++)
#pragma unroll
            for (int j = 0; j < 4; j++) s[i][j] = make_float2(0.f, 0.f);

#pragma unroll 8
        for (int kk = 0; kk < 64; kk++) {
            float4 a0 = *(const float4*)&Qs[kk][ty * 4];
            float4 a1 = *(const float4*)&Qs[kk][64 + ty * 4];
            float4 b0 = *(const float4*)&Ks[kk][tx * 4];
            float4 b1 = *(const float4*)&Ks[kk][64 + tx * 4];
            float  av[8] = {a0.x, a0.y, a0.z, a0.w, a1.x, a1.y, a1.z, a1.w};
            float2 bp[4] = {make_float2(b0.x, b0.y), make_float2(b0.z, b0.w),
                            make_float2(b1.x, b1.y), make_float2(b1.z, b1.w)};
#pragma unroll
            for (int i = 0; i < 8; i++) {
                float2 a2 = make_float2(av[i], av[i]);
#pragma unroll
                for (int j = 0; j < 4; j++) fma2(s[i][j], a2, bp[j]);
            }
        }
#pragma unroll
        for (int i = 0; i < 8; i++)
#pragma unroll
            for (int j = 0; j < 4; j++) {
                zs[i][j].x += __expf(s[i][j].x * 0.125f);
                zs[i][j].y += __expf(s[i][j].y * 0.125f);
            }
    }

#pragma unroll
    for (int i = 0; i < 8; i++) {
        int lrow = (i < 4) ? (ty * 4 + i) : (64 + ty * 4 + i - 4);
        size_t zb = ((size_t)b * Ln + (size_t)(l0 + lrow)) * Ln;
        float4 v0 = make_float4(__fdividef(1.f, zs[i][0].x), __fdividef(1.f, zs[i][0].y),
                                __fdividef(1.f, zs[i][1].x), __fdividef(1.f, zs[i][1].y));
        float4 v1 = make_float4(__fdividef(1.f, zs[i][2].x), __fdividef(1.f, zs[i][2].y),
                                __fdividef(1.f, zs[i][3].x), __fdividef(1.f, zs[i][3].y));
        *(float4*)(g_zinv + zb + m0 + tx * 4)      = v0;
        *(float4*)(g_zinv + zb + m0 + 64 + tx * 4) = v1;
    }
}

// ---------------------------------------------------------------------------
// Pass B: O_h[128,64] = sum over m-tiles [ (exp(Q K^T/8) * zinv) @ V ]
// CTA: one (b, h, 128-l-tile); m-tile = 64; writes concatted layout.
// Dynamic smem: Qs[64][132] + Ks[64][68] + Vs[64][68] + Ps[64][132] = 102400 B
// ---------------------------------------------------------------------------
__global__ __launch_bounds__(256, 2) void attn_pv_kernel()
{
    extern __shared__ float sm[];
    float (*Qs)[132] = (float(*)[132])sm;                        // k-major Q
    float (*Ks)[68]  = (float(*)[68]) (sm + 64 * 132);           // k-major K
    float (*Vs)[68]  = (float(*)[68]) (sm + 64 * 132 + 64 * 68); // m-major V
    float (*Ps)[132] = (float(*)[132])(sm + 64 * 132 + 2 * 64 * 68); // m-major P

    const int t  = threadIdx.x;
    const int tx = t & 15, ty = t >> 4;
    const int l0 = blockIdx.x * 128;
    const int h  = blockIdx.y;
    const int b  = blockIdx.z;

    const float* __restrict__ Qb = g_q + (size_t)b * LDf + (size_t)h * HSTR + (size_t)l0 * Kd;
    const float* __restrict__ Kb = g_k + (size_t)b * LDf + (size_t)h * HSTR;
    const float* __restrict__ Vb = g_v + (size_t)b * LDf + (size_t)h * HSTR;

    // Load Q tile once (transposed to k-major)
    {
        const int lr = t & 127;
        const int lc = t >> 7;
#pragma unroll
        for (int c = 0; c < 8; c++) {
            int c4 = lc + c * 2;
            float4 q = *(const float4*)(Qb + lr * Kd + c4 * 4);
            Qs[c4 * 4 + 0][lr] = q.x;  Qs[c4 * 4 + 1][lr] = q.y;
            Qs[c4 * 4 + 2][lr] = q.z;  Qs[c4 * 4 + 3][lr] = q.w;
        }
    }

    float2 o[8][2];
#pragma unroll
    for (int i = 0; i < 8; i++) { o[i][0] = make_float2(0.f, 0.f); o[i][1] = make_float2(0.f, 0.f); }

    const int mr = t & 63;     // K/V load row
    const int mc = t >> 6;     // 0..3

    for (int m0 = 0; m0 < Ln; m0 += 64) {
        __syncthreads();   // prev iteration done reading Ks/Vs (and Qs ready on iter 0)
#pragma unroll
        for (int c = 0; c < 4; c++) {
            int c4 = mc + c * 4;
            float4 kv = *(const float4*)(Kb + (size_t)(m0 + mr) * Kd + c4 * 4);
            Ks[c4 * 4 + 0][mr] = kv.x; Ks[c4 * 4 + 1][mr] = kv.y;
            Ks[c4 * 4 + 2][mr] = kv.z; Ks[c4 * 4 + 3][mr] = kv.w;
            *(float4*)&Vs[mr][c4 * 4] =
                *(const float4*)(Vb + (size_t)(m0 + mr) * Kd + c4 * 4);
        }
        __syncthreads();

        // Phase 1: S[128 l x 64 m]
        float2 s[8][2];
#pragma unroll
        for (int i = 0; i < 8; i++) { s[i][0] = make_float2(0.f, 0.f); s[i][1] = make_float2(0.f, 0.f); }

#pragma unroll 8
        for (int kk = 0; kk < 64; kk++) {
            float4 a0 = *(const float4*)&Qs[kk][ty * 4];
            float4 a1 = *(const float4*)&Qs[kk][64 + ty * 4];
            float4 b0 = *(const float4*)&Ks[kk][tx * 4];
            float  av[8] = {a0.x, a0.y, a0.z, a0.w, a1.x, a1.y, a1.z, a1.w};
            float2 bp[2] = {make_float2(b0.x, b0.y), make_float2(b0.z, b0.w)};
#pragma unroll
            for (int i = 0; i < 8; i++) {
                float2 a2 = make_float2(av[i], av[i]);
                fma2(s[i][0], a2, bp[0]);
                fma2(s[i][1], a2, bp[1]);
            }
        }

        // Phase 1b: P = exp(S/8) * zinv, stored m-major into Ps
#pragma unroll
        for (int i = 0; i < 8; i++) {
            int lrow = (i < 4) ? (ty * 4 + i) : (64 + ty * 4 + i - 4);
            float4 zv = *(const float4*)(g_zinv +
                        ((size_t)b * Ln + (size_t)(l0 + lrow)) * Ln + m0 + tx * 4);
            Ps[tx * 4 + 0][lrow] = __expf(s[i][0].x * 0.125f) * zv.x;
            Ps[tx * 4 + 1][lrow] = __expf(s[i][0].y * 0.125f) * zv.y;
            Ps[tx * 4 + 2][lrow] = __expf(s[i][1].x * 0.125f) * zv.z;
            Ps[tx * 4 + 3][lrow] = __expf(s[i][1].y * 0.125f) * zv.w;
        }
        __syncthreads();

        // Phase 2: O[128 l x 64 k] += P @ V
#pragma unroll 8
        for (int mm = 0; mm < 64; mm++) {
            float4 a0 = *(const float4*)&Ps[mm][ty * 4];
            float4 a1 = *(const float4*)&Ps[mm][64 + ty * 4];
            float4 b0 = *(const float4*)&Vs[mm][tx * 4];
            float  av[8] = {a0.x, a0.y, a0.z, a0.w, a1.x, a1.y, a1.z, a1.w};
            float2 bp[2] = {make_float2(b0.x, b0.y), make_float2(b0.z, b0.w)};
#pragma unroll
            for (int i = 0; i < 8; i++) {
                float2 a2 = make_float2(av[i], av[i]);
                fma2(o[i][0], a2, bp[0]);
                fma2(o[i][1], a2, bp[1]);
            }
        }
    }

    // Epilogue: write attended directly in concatted layout [b, l, h*64+k]
#pragma unroll
    for (int i = 0; i < 8; i++) {
        int lrow = (i < 4) ? (ty * 4 + i) : (64 + ty * 4 + i - 4);
        float4 v = make_float4(o[i][0].x, o[i][0].y, o[i][1].x, o[i][1].y);
        *(float4*)(g_att + (size_t)b * LDf + (size_t)(l0 + lrow) * 1024 + h * 64 + tx * 4) = v;
    }
}

// ---------------------------------------------------------------------------
// Launch
// ---------------------------------------------------------------------------
extern "C" void kernel_launch(void* const* d_in, const int* in_sizes, int n_in,
                              void* d_out, int out_size)
{
    const float* x    = (const float*)d_in[0];
    const float* wqkv = (const float*)d_in[1];
    const float* wo   = (const float*)d_in[2];
    float* out = (float*)d_out;

    // 1) QKV projection: [8192,1024] @ [1024,3072] -> g_q/g_k/g_v
    sgemm128<<<dim3(24, 64), 256>>>(x, wqkv, nullptr, 3072, 0);

    // 2) Pass A: head-coupled softmax denominators -> g_zinv
    cudaFuncSetAttribute(zsum_kernel, cudaFuncAttributeMaxDynamicSharedMemorySize, 67584);
    zsum_kernel<<<dim3(16, 16, 4), 256, 67584>>>();

    // 3) Pass B: per-head P@V with normalization -> g_att (concatted layout)
    cudaFuncSetAttribute(attn_pv_kernel, cudaFuncAttributeMaxDynamicSharedMemorySize, 102400);
    attn_pv_kernel<<<dim3(16, 16, 4), 256, 102400>>>();

    // 4) Output projection: [8192,1024] @ [1024,1024] -> d_out
    sgemm128<<<dim3(8, 64), 256>>>(nullptr, wo, out, 1024, 1);
}